// round 13
// baseline (speedup 1.0000x reference)
#include <cuda_runtime.h>
#include <cuda_bf16.h>
#include <math.h>
#include <stdint.h>

// Problem constants
#define BB 16      // batch
#define LL 512     // seq len
#define HH 1024    // hidden
#define PP 5       // max phrase len
#define KK 16      // top-k
#define PDD 128    // phrase dim
#define NN 3072    // combined GEMM output cols (S | E | M)
#define MM (BB*LL) // 8192 gemm rows
#define KSPLIT 3072 // packed split-K: [Ah | Al | Ah] x [Bh | Bh | Bl]

// Output layout: phrase[16,16,128] | pmask[16,16] | attn[16,16] | top_scores[16,16]
#define OFF_PMASK   (BB*KK*PDD)          // 32768
#define OFF_ATTN    (OFF_PMASK + BB*KK)  // 33024
#define OFF_TSCORE  (OFF_ATTN + BB*KK)   // 33280

// Scratch (static device globals — no allocation allowed)
__device__ __align__(16) __nv_bfloat16 g_Abf[(size_t)MM * KSPLIT]; // 48 MB  A' split
__device__ __align__(16) __nv_bfloat16 g_Bbf[(size_t)NN * KSPLIT]; // 18 MB  B' split (U^T)
__device__ float g_Y[(size_t)MM * NN];                             // 96 MB  S|E|M rows
__device__ float g_scores[BB * LL * PP];
__device__ int   g_topidx[BB * KK];

// ===========================================================================
// mma.sync / cp.async helpers (base ISA, works on plain sm_100 target)
// ===========================================================================
__device__ __forceinline__ uint32_t smem_u32(const void* p) {
    uint32_t a;
    asm("{ .reg .u64 t; cvta.to.shared.u64 t, %1; cvt.u32.u64 %0, t; }" : "=r"(a) : "l"(p));
    return a;
}
#define LDSM_X4(r, addr) \
    asm volatile("ldmatrix.sync.aligned.m8n8.x4.shared.b16 {%0,%1,%2,%3}, [%4];" \
        : "=r"((r)[0]), "=r"((r)[1]), "=r"((r)[2]), "=r"((r)[3]) : "r"(addr))
#define MMA16816(c, A, b0v, b1v) \
    asm volatile("mma.sync.aligned.m16n8k16.row.col.f32.bf16.bf16.f32 " \
        "{%0,%1,%2,%3}, {%4,%5,%6,%7}, {%8,%9}, {%0,%1,%2,%3};" \
        : "+f"((c)[0]), "+f"((c)[1]), "+f"((c)[2]), "+f"((c)[3]) \
        : "r"((A)[0]), "r"((A)[1]), "r"((A)[2]), "r"((A)[3]), "r"(b0v), "r"(b1v))
#define CP_ASYNC16(saddr, gptr) \
    asm volatile("cp.async.cg.shared.global [%0], [%1], 16;" :: "r"(saddr), "l"(gptr) : "memory")
#define CP_COMMIT() asm volatile("cp.async.commit_group;" ::: "memory")
#define CP_WAIT0()  asm volatile("cp.async.wait_group 0;" ::: "memory")

// ===========================================================================
// prep_b (fused prep_u + conv_b): build U = [A1-A4 | A2+A4 | A3] tile in smem
// directly from w1 [4096,1024], transpose, emit bf16 hi/lo into
// g_Bbf [3072 n, 3072 k'] = [Bh | Bh | Bl]. No g_U round-trip.
// feat = [start; end; mean; end-start] is linear in 3 vectors:
//   W1^T feat = (A1-A4)^T start + (A2+A4)^T end + A3^T mean
// ===========================================================================
__global__ void prep_b_kernel(const float* __restrict__ w1) {
    __shared__ float t[32][33];
    int n0 = blockIdx.x * 32, k0 = blockIdx.y * 32;
    int tx = threadIdx.x, ty = threadIdx.y;
    int r = k0 + ty;            // U row = input dim k
    int n = n0 + tx;            // U col = output n
    float v;
    if (n < 1024) {
        v = w1[r * HH + n] - w1[(3072 + r) * HH + n];
    } else if (n < 2048) {
        int h = n - 1024;
        v = w1[(1024 + r) * HH + h] + w1[(3072 + r) * HH + h];
    } else {
        int h = n - 2048;
        v = w1[(2048 + r) * HH + h];
    }
    t[ty][tx] = v;
    __syncthreads();
    float u = t[tx][ty];        // = U[k0+tx][n0+ty]
    __nv_bfloat16 hi = __float2bfloat16(u);
    __nv_bfloat16 lo = __float2bfloat16(u - __bfloat162float(hi));
    size_t base = (size_t)(n0 + ty) * KSPLIT + k0 + tx;
    g_Bbf[base]        = hi;
    g_Bbf[base + 1024] = hi;
    g_Bbf[base + 2048] = lo;
}

// ===========================================================================
// conv_a: hidden fp32 [8192,1024] -> A' bf16 [8192, 3072] = [Ah | Al | Ah]
// ===========================================================================
__global__ void conv_a_kernel(const float* __restrict__ hidden) {
    int i = blockIdx.x * blockDim.x + threadIdx.x;   // one thread per 4 elems
    if (i >= MM * HH / 4) return;
    int r = i / (HH / 4);
    int k = (i % (HH / 4)) * 4;
    float4 v = *(const float4*)&hidden[(size_t)r * HH + k];
    __nv_bfloat16 h[4], l[4];
    float f[4] = {v.x, v.y, v.z, v.w};
    #pragma unroll
    for (int j = 0; j < 4; j++) {
        h[j] = __float2bfloat16(f[j]);
        l[j] = __float2bfloat16(f[j] - __bfloat162float(h[j]));
    }
    size_t base = (size_t)r * KSPLIT + k;
    *(uint2*)&g_Abf[base]        = *(uint2*)h;   // Ah
    *(uint2*)&g_Abf[base + 1024] = *(uint2*)l;   // Al
    *(uint2*)&g_Abf[base + 2048] = *(uint2*)h;   // Ah (dup for Ah*Bl term)
}

// ===========================================================================
// Tensor-core GEMM: g_Y[8192,3072] = A'[8192,3072] @ B'[3072,3072]^T
// (both K-major). mma.sync m16n8k16 bf16, fp32 acc.
// CTA tile 128x128, BK=96 (32 chunks instead of 48 -> 33% fewer barrier
// rounds), 256 threads = 8 warps (4 M x 2 N), warp tile 32x64.
// 2-stage cp.async double buffer (104 KB) -> 2 CTAs/SM = 16 warps/SM.
// Rows padded to 104 bf16 (208 B = 52 words === 20 mod 32): ldsm 8-row
// groups hit banks {0,20,8,28,16,4,24,12} -> conflict-free.
// ===========================================================================
#define TM 128
#define TN 128
#define BKC 96
#define NKT (KSPLIT / BKC)   // 32
#define PAD 104
#define ABUF_BYTES (128 * PAD * 2)             // 26624
#define GSMEM_SZ   (4 * ABUF_BYTES)            // 106496 (A0,A1,B0,B1)

__global__ __launch_bounds__(256, 2) void gemm_mma_kernel() {
    extern __shared__ char smem[];
    const int tid = threadIdx.x;
    const int lane = tid & 31, wid = tid >> 5;
    const int wm = wid >> 1, wn = wid & 1;       // 4x2 warp grid, 32x64 tiles
    const int bm = blockIdx.y * TM, bn = blockIdx.x * TN;
    const uint32_t sb = smem_u32(smem);

    #define SA(s)   ((uint32_t)((s) * ABUF_BYTES))
    #define SBUF(s) ((uint32_t)(2 * ABUF_BYTES + (s) * ABUF_BYTES))

    float acc[2][8][4];
    #pragma unroll
    for (int i = 0; i < 2; i++)
        #pragma unroll
        for (int j = 0; j < 8; j++)
            #pragma unroll
            for (int q = 0; q < 4; q++) acc[i][j][q] = 0.f;

    // cp.async fill: 128 rows x 12 16B-chunks = 1536 chunks/tile, 6 per thread
    auto load_stage = [&](int kt, int buf) {
        size_t ko = (size_t)kt * BKC;
        #pragma unroll
        for (int it = 0; it < 6; it++) {
            int id = tid + it * 256;
            int r = id / 12, kc = (id % 12) * 8;
            CP_ASYNC16(sb + SA(buf) + (uint32_t)(r * PAD + kc) * 2,
                       &g_Abf[(size_t)(bm + r) * KSPLIT + ko + kc]);
            CP_ASYNC16(sb + SBUF(buf) + (uint32_t)(r * PAD + kc) * 2,
                       &g_Bbf[(size_t)(bn + r) * KSPLIT + ko + kc]);
        }
        CP_COMMIT();
    };

    load_stage(0, 0);

    // per-thread ldmatrix pieces
    const int rowsel = lane & 15;
    const int kl = (lane >> 4) * 8;   // k half-select

    for (int kt = 0; kt < NKT; kt++) {
        CP_WAIT0();
        __syncthreads();
        if (kt + 1 < NKT) load_stage(kt + 1, (kt + 1) & 1);

        const int cur = kt & 1;
        const uint32_t abase = sb + SA(cur);
        const uint32_t bbase = sb + SBUF(cur);
        #pragma unroll
        for (int kk = 0; kk < BKC; kk += 16) {
            uint32_t af[2][4], bf[4][4];
            #pragma unroll
            for (int mi = 0; mi < 2; mi++)
                LDSM_X4(af[mi], abase + (uint32_t)((wm * 32 + mi * 16 + rowsel) * PAD + kk + kl) * 2);
            #pragma unroll
            for (int nj = 0; nj < 4; nj++)
                LDSM_X4(bf[nj], bbase + (uint32_t)((wn * 64 + nj * 16 + rowsel) * PAD + kk + kl) * 2);
            #pragma unroll
            for (int mi = 0; mi < 2; mi++) {
                #pragma unroll
                for (int nj = 0; nj < 4; nj++) {
                    MMA16816(acc[mi][2 * nj],     af[mi], bf[nj][0], bf[nj][2]);
                    MMA16816(acc[mi][2 * nj + 1], af[mi], bf[nj][1], bf[nj][3]);
                }
            }
        }
        // next iteration's CP_WAIT0 + sync guards buffer reuse
    }

    // epilogue: rows bm+wm*32+mi*16+(lane>>2)(+8), cols bn+wn*64+ni*8+2*(lane&3)
    #pragma unroll
    for (int mi = 0; mi < 2; mi++) {
        int gm = bm + wm * 32 + mi * 16 + (lane >> 2);
        #pragma unroll
        for (int ni = 0; ni < 8; ni++) {
            int gn = bn + wn * 64 + ni * 8 + 2 * (lane & 3);
            *(float2*)&g_Y[(size_t)gm * NN + gn] =
                make_float2(acc[mi][ni][0], acc[mi][ni][1]);
            *(float2*)&g_Y[(size_t)(gm + 8) * NN + gn] =
                make_float2(acc[mi][ni][2], acc[mi][ni][3]);
        }
    }
}

// ===========================================================================
// Scoring: z = S[l] + E[e] + (sum M[l..l+p])/(p+1) + b1;
// score = sum relu(z)*w2 + b2 (or -inf). One block per (b,l).
// ===========================================================================
__global__ __launch_bounds__(256) void score_kernel(const float* __restrict__ b1,
                                                    const float* __restrict__ w2,
                                                    const float* __restrict__ b2,
                                                    const int* __restrict__ lengths) {
    int l = blockIdx.x;
    int b = blockIdx.y;
    int tid = threadIdx.x;
    size_t rowbase = (size_t)(b * LL + l) * NN;

    int h0 = tid, h1 = tid + 256, h2 = tid + 512, h3 = tid + 768;
    float s0 = g_Y[rowbase + h0], s1 = g_Y[rowbase + h1];
    float s2 = g_Y[rowbase + h2], s3 = g_Y[rowbase + h3];
    float w0 = w2[h0], w1v = w2[h1], w2v = w2[h2], w3v = w2[h3];
    float c0 = b1[h0], c1 = b1[h1], c2 = b1[h2], c3 = b1[h3];
    float m0 = 0.f, m1 = 0.f, m2 = 0.f, m3 = 0.f;

    float acc[PP];
    #pragma unroll
    for (int p = 0; p < PP; p++) {
        int t = l + p;
        if (t <= LL - 1) {
            size_t mb = (size_t)(b * LL + t) * NN + 2048;
            m0 += g_Y[mb + h0]; m1 += g_Y[mb + h1];
            m2 += g_Y[mb + h2]; m3 += g_Y[mb + h3];
        }
        int e = min(t, LL - 1);
        size_t eb = (size_t)(b * LL + e) * NN + 1024;
        float inv = 1.f / (float)(p + 1);
        float z0 = s0 + g_Y[eb + h0] + m0 * inv + c0;
        float z1 = s1 + g_Y[eb + h1] + m1 * inv + c1;
        float z2 = s2 + g_Y[eb + h2] + m2 * inv + c2;
        float z3 = s3 + g_Y[eb + h3] + m3 * inv + c3;
        acc[p] = fmaxf(z0, 0.f) * w0 + fmaxf(z1, 0.f) * w1v
               + fmaxf(z2, 0.f) * w2v + fmaxf(z3, 0.f) * w3v;
    }

    __shared__ float red[8][PP];
    int lane = tid & 31, warp = tid >> 5;
    #pragma unroll
    for (int p = 0; p < PP; p++) {
        float v = acc[p];
        for (int o = 16; o; o >>= 1) v += __shfl_down_sync(0xffffffffu, v, o);
        if (lane == 0) red[warp][p] = v;
    }
    __syncthreads();
    if (tid < PP) {
        float v = 0.f;
        #pragma unroll
        for (int w = 0; w < 8; w++) v += red[w][tid];
        int len = lengths[b];
        float bias2 = b2[0];
        g_scores[b * (LL * PP) + l * PP + tid] =
            (l + tid < len) ? (v + bias2) : -INFINITY;
    }
}

// ===========================================================================
// Top-K per batch (iterative argmax, ties -> lower index)
// ===========================================================================
__global__ void topk_kernel(float* __restrict__ out) {
    int b = blockIdx.x;
    int tid = threadIdx.x;  // 256
    __shared__ float sv[LL * PP];
    __shared__ float bv[256];
    __shared__ int   bi[256];
    for (int i = tid; i < LL * PP; i += 256) sv[i] = g_scores[b * (LL * PP) + i];
    __syncthreads();
    for (int k = 0; k < KK; k++) {
        float best = -INFINITY; int besti = 0x7fffffff;
        for (int i = tid; i < LL * PP; i += 256) {
            float v = sv[i];
            if (v > best || (v == best && i < besti)) { best = v; besti = i; }
        }
        bv[tid] = best; bi[tid] = besti;
        __syncthreads();
        for (int s = 128; s; s >>= 1) {
            if (tid < s) {
                if (bv[tid + s] > bv[tid] ||
                    (bv[tid + s] == bv[tid] && bi[tid + s] < bi[tid])) {
                    bv[tid] = bv[tid + s]; bi[tid] = bi[tid + s];
                }
            }
            __syncthreads();
        }
        if (tid == 0) {
            g_topidx[b * KK + k] = bi[0];
            out[OFF_TSCORE + b * KK + k] = bv[0];
            sv[bi[0]] = -INFINITY;
        }
        __syncthreads();
    }
}

// ===========================================================================
// Fused tail: one block per batch b (512 threads).
//  1. embs[k,:] = mean of hidden rows (into 64KB smem; no global round-trip)
//  2. G1 = tanh(embs @ gw1 + gb1), gate = G1 @ gw2 + gb2 (block reduction)
//  3. attn = softmax(gate), pmask = 1
//  4. phrase = embs @ pw + pb
// ===========================================================================
#define TAIL_SMEM (KK * HH * 4 + KK * 16 * 4)   // 65536 + 1024

__global__ __launch_bounds__(512) void tail_kernel(const float* __restrict__ hidden,
                                                   const float* __restrict__ gw1,
                                                   const float* __restrict__ gb1,
                                                   const float* __restrict__ gw2,
                                                   const float* __restrict__ gb2,
                                                   const float* __restrict__ pw,
                                                   const float* __restrict__ pb,
                                                   float* __restrict__ out) {
    extern __shared__ float tsm[];
    float* embs_s = tsm;                    // [KK][HH]
    float* red    = tsm + KK * HH;          // [KK][16]
    int b = blockIdx.x;
    int tid = threadIdx.x;
    int lane = tid & 31, warp = tid >> 5;   // 16 warps

    // 1. embs (each thread: 2 h-values per k)
    #pragma unroll
    for (int k = 0; k < KK; k++) {
        int idx = g_topidx[b * KK + k];
        int l = idx / PP, p = idx % PP;
        int e = min(l + p, LL - 1);
        float inv = 1.f / (float)(p + 1);
        #pragma unroll
        for (int i = 0; i < 2; i++) {
            int h = tid + i * 512;
            float s = 0.f;
            for (int t = l; t <= e; t++) s += hidden[((size_t)(b * LL + t)) * HH + h];
            embs_s[k * HH + h] = s * inv;
        }
    }
    __syncthreads();

    // 2. g1 + gate partials: o = tid
    {
        float tacc[KK];
        #pragma unroll
        for (int k = 0; k < KK; k++) tacc[k] = 0.f;
        for (int m = 0; m < HH; m++) {
            float g = gw1[(size_t)m * 512 + tid];
            #pragma unroll
            for (int k = 0; k < KK; k++) tacc[k] = fmaf(embs_s[k * HH + m], g, tacc[k]);
        }
        float gb = gb1[tid], gv = gw2[tid];
        float part[KK];
        #pragma unroll
        for (int k = 0; k < KK; k++) part[k] = tanhf(tacc[k] + gb) * gv;
        // warp reduce each k, then cross-warp via smem
        #pragma unroll
        for (int k = 0; k < KK; k++) {
            float v = part[k];
            for (int o = 16; o; o >>= 1) v += __shfl_down_sync(0xffffffffu, v, o);
            if (lane == 0) red[k * 16 + warp] = v;
        }
    }
    __syncthreads();
    if (tid == 0) {
        float gate[KK];
        float g2b = gb2[0];
        #pragma unroll
        for (int k = 0; k < KK; k++) {
            float v = 0.f;
            #pragma unroll
            for (int w = 0; w < 16; w++) v += red[k * 16 + w];
            gate[k] = v + g2b;
        }
        float mx = gate[0];
        #pragma unroll
        for (int k = 1; k < KK; k++) mx = fmaxf(mx, gate[k]);
        float ex[KK], ssum = 0.f;
        #pragma unroll
        for (int k = 0; k < KK; k++) { ex[k] = expf(gate[k] - mx); ssum += ex[k]; }
        float rs = 1.f / ssum;
        #pragma unroll
        for (int k = 0; k < KK; k++) {
            out[OFF_ATTN + b * KK + k] = ex[k] * rs;
            out[OFF_PMASK + b * KK + k] = 1.0f;
        }
    }

    // 4. phrase: d = tid&127, kg = tid>>7 handles k = j*4+kg
    {
        int d = tid & 127, kg = tid >> 7;
        float pacc[4] = {0.f, 0.f, 0.f, 0.f};
        for (int m = 0; m < HH; m++) {
            float pv = pw[(size_t)m * PDD + d];
            #pragma unroll
            for (int j = 0; j < 4; j++)
                pacc[j] = fmaf(embs_s[(j * 4 + kg) * HH + m], pv, pacc[j]);
        }
        float pbv = pb[d];
        #pragma unroll
        for (int j = 0; j < 4; j++)
            out[(size_t)(b * KK + j * 4 + kg) * PDD + d] = pacc[j] + pbv;
    }
}

// ===========================================================================
extern "C" void kernel_launch(void* const* d_in, const int* in_sizes, int n_in,
                              void* d_out, int out_size) {
    const float* hidden  = (const float*)d_in[0];
    const int*   lengths = (const int*)  d_in[1];
    const float* w1      = (const float*)d_in[2];
    const float* b1      = (const float*)d_in[3];
    const float* w2      = (const float*)d_in[4];
    const float* b2      = (const float*)d_in[5];
    const float* gw1     = (const float*)d_in[6];
    const float* gb1     = (const float*)d_in[7];
    const float* gw2     = (const float*)d_in[8];
    const float* gb2     = (const float*)d_in[9];
    const float* pw      = (const float*)d_in[10];
    const float* pb      = (const float*)d_in[11];
    float* out = (float*)d_out;

    cudaFuncSetAttribute(gemm_mma_kernel, cudaFuncAttributeMaxDynamicSharedMemorySize, GSMEM_SZ);
    cudaFuncSetAttribute(tail_kernel, cudaFuncAttributeMaxDynamicSharedMemorySize, TAIL_SMEM);

    prep_b_kernel<<<dim3(NN / 32, HH / 32), dim3(32, 32)>>>(w1);
    conv_a_kernel<<<(MM * HH / 4 + 255) / 256, 256>>>(hidden);
    gemm_mma_kernel<<<dim3(NN / TN, MM / TM), 256, GSMEM_SZ>>>();
    score_kernel<<<dim3(LL, BB), 256>>>(b1, w2, b2, lengths);
    topk_kernel<<<BB, 256>>>(out);
    tail_kernel<<<BB, 512, TAIL_SMEM>>>(hidden, gw1, gb1, gw2, gb2, pw, pb, out);
}

// round 14
// speedup vs baseline: 1.0369x; 1.0369x over previous
#include <cuda_runtime.h>
#include <cuda_bf16.h>
#include <math.h>
#include <stdint.h>

// Problem constants
#define BB 16      // batch
#define LL 512     // seq len
#define HH 1024    // hidden
#define PP 5       // max phrase len
#define KK 16      // top-k
#define PDD 128    // phrase dim
#define NN 3072    // combined GEMM output cols (S | E | M)
#define MM (BB*LL) // 8192 gemm rows
#define KSPLIT 3072 // packed split-K: [Ah | Al | Ah] x [Bh | Bh | Bl]

// Output layout: phrase[16,16,128] | pmask[16,16] | attn[16,16] | top_scores[16,16]
#define OFF_PMASK   (BB*KK*PDD)          // 32768
#define OFF_ATTN    (OFF_PMASK + BB*KK)  // 33024
#define OFF_TSCORE  (OFF_ATTN + BB*KK)   // 33280

// Scratch (static device globals — no allocation allowed)
__device__ __align__(16) __nv_bfloat16 g_Abf[(size_t)MM * KSPLIT]; // 48 MB  A' split
__device__ __align__(16) __nv_bfloat16 g_Bbf[(size_t)NN * KSPLIT]; // 18 MB  B' split (U^T)
__device__ float g_Y[(size_t)MM * NN];                             // 96 MB  S|E|M rows
__device__ float g_scores[BB * LL * PP];
__device__ int   g_topidx[BB * KK];

// ===========================================================================
// mma.sync / cp.async helpers (base ISA, works on plain sm_100 target)
// ===========================================================================
__device__ __forceinline__ uint32_t smem_u32(const void* p) {
    uint32_t a;
    asm("{ .reg .u64 t; cvta.to.shared.u64 t, %1; cvt.u32.u64 %0, t; }" : "=r"(a) : "l"(p));
    return a;
}
#define LDSM_X4(r, addr) \
    asm volatile("ldmatrix.sync.aligned.m8n8.x4.shared.b16 {%0,%1,%2,%3}, [%4];" \
        : "=r"((r)[0]), "=r"((r)[1]), "=r"((r)[2]), "=r"((r)[3]) : "r"(addr))
#define MMA16816(c, A, b0v, b1v) \
    asm volatile("mma.sync.aligned.m16n8k16.row.col.f32.bf16.bf16.f32 " \
        "{%0,%1,%2,%3}, {%4,%5,%6,%7}, {%8,%9}, {%0,%1,%2,%3};" \
        : "+f"((c)[0]), "+f"((c)[1]), "+f"((c)[2]), "+f"((c)[3]) \
        : "r"((A)[0]), "r"((A)[1]), "r"((A)[2]), "r"((A)[3]), "r"(b0v), "r"(b1v))
#define CP_ASYNC16(saddr, gptr) \
    asm volatile("cp.async.cg.shared.global [%0], [%1], 16;" :: "r"(saddr), "l"(gptr) : "memory")
#define CP_COMMIT() asm volatile("cp.async.commit_group;" ::: "memory")
#define CP_WAIT0()  asm volatile("cp.async.wait_group 0;" ::: "memory")

// ===========================================================================
// prep_b (fused prep_u + conv_b): build U = [A1-A4 | A2+A4 | A3] tile in smem
// directly from w1 [4096,1024], transpose, emit bf16 hi/lo into
// g_Bbf [3072 n, 3072 k'] = [Bh | Bh | Bl]. No g_U round-trip.
// feat = [start; end; mean; end-start] is linear in 3 vectors:
//   W1^T feat = (A1-A4)^T start + (A2+A4)^T end + A3^T mean
// ===========================================================================
__global__ void prep_b_kernel(const float* __restrict__ w1) {
    __shared__ float t[32][33];
    int n0 = blockIdx.x * 32, k0 = blockIdx.y * 32;
    int tx = threadIdx.x, ty = threadIdx.y;
    int r = k0 + ty;            // U row = input dim k
    int n = n0 + tx;            // U col = output n
    float v;
    if (n < 1024) {
        v = w1[r * HH + n] - w1[(3072 + r) * HH + n];
    } else if (n < 2048) {
        int h = n - 1024;
        v = w1[(1024 + r) * HH + h] + w1[(3072 + r) * HH + h];
    } else {
        int h = n - 2048;
        v = w1[(2048 + r) * HH + h];
    }
    t[ty][tx] = v;
    __syncthreads();
    float u = t[tx][ty];        // = U[k0+tx][n0+ty]
    __nv_bfloat16 hi = __float2bfloat16(u);
    __nv_bfloat16 lo = __float2bfloat16(u - __bfloat162float(hi));
    size_t base = (size_t)(n0 + ty) * KSPLIT + k0 + tx;
    g_Bbf[base]        = hi;
    g_Bbf[base + 1024] = hi;
    g_Bbf[base + 2048] = lo;
}

// ===========================================================================
// conv_a: hidden fp32 [8192,1024] -> A' bf16 [8192, 3072] = [Ah | Al | Ah]
// ===========================================================================
__global__ void conv_a_kernel(const float* __restrict__ hidden) {
    int i = blockIdx.x * blockDim.x + threadIdx.x;   // one thread per 4 elems
    if (i >= MM * HH / 4) return;
    int r = i / (HH / 4);
    int k = (i % (HH / 4)) * 4;
    float4 v = *(const float4*)&hidden[(size_t)r * HH + k];
    __nv_bfloat16 h[4], l[4];
    float f[4] = {v.x, v.y, v.z, v.w};
    #pragma unroll
    for (int j = 0; j < 4; j++) {
        h[j] = __float2bfloat16(f[j]);
        l[j] = __float2bfloat16(f[j] - __bfloat162float(h[j]));
    }
    size_t base = (size_t)r * KSPLIT + k;
    *(uint2*)&g_Abf[base]        = *(uint2*)h;   // Ah
    *(uint2*)&g_Abf[base + 1024] = *(uint2*)l;   // Al
    *(uint2*)&g_Abf[base + 2048] = *(uint2*)h;   // Ah (dup for Ah*Bl term)
}

// ===========================================================================
// Tensor-core GEMM: g_Y[8192,3072] = A'[8192,3072] @ B'[3072,3072]^T
// (both K-major). mma.sync m16n8k16 bf16, fp32 acc.
// R12-measured best config: CTA tile 128x128, BK=64, 256 threads = 8 warps
// (4 M x 2 N), warp tile 32x64. 2-stage cp.async double buffer (73.7 KB)
// -> 2 CTAs/SM = 16 warps/SM. Rows padded to 72 bf16: conflict-free ldsm.
// ===========================================================================
#define TM 128
#define TN 128
#define BKC 64
#define NKT (KSPLIT / BKC)   // 48
#define PAD 72
#define ABUF_BYTES (128 * PAD * 2)             // 18432
#define GSMEM_SZ   (4 * ABUF_BYTES)            // 73728 (A0,A1,B0,B1)

__global__ __launch_bounds__(256, 2) void gemm_mma_kernel() {
    extern __shared__ char smem[];
    const int tid = threadIdx.x;
    const int lane = tid & 31, wid = tid >> 5;
    const int wm = wid >> 1, wn = wid & 1;       // 4x2 warp grid, 32x64 tiles
    const int bm = blockIdx.y * TM, bn = blockIdx.x * TN;
    const uint32_t sb = smem_u32(smem);

    #define SA(s)   ((uint32_t)((s) * ABUF_BYTES))
    #define SBUF(s) ((uint32_t)(2 * ABUF_BYTES + (s) * ABUF_BYTES))

    float acc[2][8][4];
    #pragma unroll
    for (int i = 0; i < 2; i++)
        #pragma unroll
        for (int j = 0; j < 8; j++)
            #pragma unroll
            for (int q = 0; q < 4; q++) acc[i][j][q] = 0.f;

    // cp.async fill: 1024 16B chunks per tile, 256 threads -> 4 chunks each
    auto load_stage = [&](int kt, int buf) {
        size_t ko = (size_t)kt * BKC;
        #pragma unroll
        for (int it = 0; it < 4; it++) {
            int id = tid + it * 256;
            int r = id >> 3, kc = (id & 7) * 8;
            CP_ASYNC16(sb + SA(buf) + (uint32_t)(r * PAD + kc) * 2,
                       &g_Abf[(size_t)(bm + r) * KSPLIT + ko + kc]);
            CP_ASYNC16(sb + SBUF(buf) + (uint32_t)(r * PAD + kc) * 2,
                       &g_Bbf[(size_t)(bn + r) * KSPLIT + ko + kc]);
        }
        CP_COMMIT();
    };

    load_stage(0, 0);

    // per-thread ldmatrix pieces
    const int rowsel = lane & 15;
    const int kl = (lane >> 4) * 8;   // k half-select

    for (int kt = 0; kt < NKT; kt++) {
        CP_WAIT0();
        __syncthreads();
        if (kt + 1 < NKT) load_stage(kt + 1, (kt + 1) & 1);

        const int cur = kt & 1;
        const uint32_t abase = sb + SA(cur);
        const uint32_t bbase = sb + SBUF(cur);
        #pragma unroll
        for (int kk = 0; kk < BKC; kk += 16) {
            uint32_t af[2][4], bf[4][4];
            #pragma unroll
            for (int mi = 0; mi < 2; mi++)
                LDSM_X4(af[mi], abase + (uint32_t)((wm * 32 + mi * 16 + rowsel) * PAD + kk + kl) * 2);
            #pragma unroll
            for (int nj = 0; nj < 4; nj++)
                LDSM_X4(bf[nj], bbase + (uint32_t)((wn * 64 + nj * 16 + rowsel) * PAD + kk + kl) * 2);
            #pragma unroll
            for (int mi = 0; mi < 2; mi++) {
                #pragma unroll
                for (int nj = 0; nj < 4; nj++) {
                    MMA16816(acc[mi][2 * nj],     af[mi], bf[nj][0], bf[nj][2]);
                    MMA16816(acc[mi][2 * nj + 1], af[mi], bf[nj][1], bf[nj][3]);
                }
            }
        }
        // next iteration's CP_WAIT0 + sync guards buffer reuse
    }

    // epilogue: rows bm+wm*32+mi*16+(lane>>2)(+8), cols bn+wn*64+ni*8+2*(lane&3)
    #pragma unroll
    for (int mi = 0; mi < 2; mi++) {
        int gm = bm + wm * 32 + mi * 16 + (lane >> 2);
        #pragma unroll
        for (int ni = 0; ni < 8; ni++) {
            int gn = bn + wn * 64 + ni * 8 + 2 * (lane & 3);
            *(float2*)&g_Y[(size_t)gm * NN + gn] =
                make_float2(acc[mi][ni][0], acc[mi][ni][1]);
            *(float2*)&g_Y[(size_t)(gm + 8) * NN + gn] =
                make_float2(acc[mi][ni][2], acc[mi][ni][3]);
        }
    }
}

// ===========================================================================
// Scoring: z = S[l] + E[e] + (sum M[l..l+p])/(p+1) + b1;
// score = sum relu(z)*w2 + b2 (or -inf). One block per (b,l).
// ===========================================================================
__global__ __launch_bounds__(256) void score_kernel(const float* __restrict__ b1,
                                                    const float* __restrict__ w2,
                                                    const float* __restrict__ b2,
                                                    const int* __restrict__ lengths) {
    int l = blockIdx.x;
    int b = blockIdx.y;
    int tid = threadIdx.x;
    size_t rowbase = (size_t)(b * LL + l) * NN;

    int h0 = tid, h1 = tid + 256, h2 = tid + 512, h3 = tid + 768;
    float s0 = g_Y[rowbase + h0], s1 = g_Y[rowbase + h1];
    float s2 = g_Y[rowbase + h2], s3 = g_Y[rowbase + h3];
    float w0 = w2[h0], w1v = w2[h1], w2v = w2[h2], w3v = w2[h3];
    float c0 = b1[h0], c1 = b1[h1], c2 = b1[h2], c3 = b1[h3];
    float m0 = 0.f, m1 = 0.f, m2 = 0.f, m3 = 0.f;

    float acc[PP];
    #pragma unroll
    for (int p = 0; p < PP; p++) {
        int t = l + p;
        if (t <= LL - 1) {
            size_t mb = (size_t)(b * LL + t) * NN + 2048;
            m0 += g_Y[mb + h0]; m1 += g_Y[mb + h1];
            m2 += g_Y[mb + h2]; m3 += g_Y[mb + h3];
        }
        int e = min(t, LL - 1);
        size_t eb = (size_t)(b * LL + e) * NN + 1024;
        float inv = 1.f / (float)(p + 1);
        float z0 = s0 + g_Y[eb + h0] + m0 * inv + c0;
        float z1 = s1 + g_Y[eb + h1] + m1 * inv + c1;
        float z2 = s2 + g_Y[eb + h2] + m2 * inv + c2;
        float z3 = s3 + g_Y[eb + h3] + m3 * inv + c3;
        acc[p] = fmaxf(z0, 0.f) * w0 + fmaxf(z1, 0.f) * w1v
               + fmaxf(z2, 0.f) * w2v + fmaxf(z3, 0.f) * w3v;
    }

    __shared__ float red[8][PP];
    int lane = tid & 31, warp = tid >> 5;
    #pragma unroll
    for (int p = 0; p < PP; p++) {
        float v = acc[p];
        for (int o = 16; o; o >>= 1) v += __shfl_down_sync(0xffffffffu, v, o);
        if (lane == 0) red[warp][p] = v;
    }
    __syncthreads();
    if (tid < PP) {
        float v = 0.f;
        #pragma unroll
        for (int w = 0; w < 8; w++) v += red[w][tid];
        int len = lengths[b];
        float bias2 = b2[0];
        g_scores[b * (LL * PP) + l * PP + tid] =
            (l + tid < len) ? (v + bias2) : -INFINITY;
    }
}

// ===========================================================================
// Top-K per batch (iterative argmax, ties -> lower index)
// ===========================================================================
__global__ void topk_kernel(float* __restrict__ out) {
    int b = blockIdx.x;
    int tid = threadIdx.x;  // 256
    __shared__ float sv[LL * PP];
    __shared__ float bv[256];
    __shared__ int   bi[256];
    for (int i = tid; i < LL * PP; i += 256) sv[i] = g_scores[b * (LL * PP) + i];
    __syncthreads();
    for (int k = 0; k < KK; k++) {
        float best = -INFINITY; int besti = 0x7fffffff;
        for (int i = tid; i < LL * PP; i += 256) {
            float v = sv[i];
            if (v > best || (v == best && i < besti)) { best = v; besti = i; }
        }
        bv[tid] = best; bi[tid] = besti;
        __syncthreads();
        for (int s = 128; s; s >>= 1) {
            if (tid < s) {
                if (bv[tid + s] > bv[tid] ||
                    (bv[tid + s] == bv[tid] && bi[tid + s] < bi[tid])) {
                    bv[tid] = bv[tid + s]; bi[tid] = bi[tid + s];
                }
            }
            __syncthreads();
        }
        if (tid == 0) {
            g_topidx[b * KK + k] = bi[0];
            out[OFF_TSCORE + b * KK + k] = bv[0];
            sv[bi[0]] = -INFINITY;
        }
        __syncthreads();
    }
}

// ===========================================================================
// Fused tail: one block per batch b (512 threads).
//  1. embs[k,:] = mean of hidden rows (into 64KB smem; no global round-trip)
//  2. G1 = tanh(embs @ gw1 + gb1), gate = G1 @ gw2 + gb2 (block reduction)
//  3. attn = softmax(gate), pmask = 1
//  4. phrase = embs @ pw + pb
// ===========================================================================
#define TAIL_SMEM (KK * HH * 4 + KK * 16 * 4)   // 65536 + 1024

__global__ __launch_bounds__(512) void tail_kernel(const float* __restrict__ hidden,
                                                   const float* __restrict__ gw1,
                                                   const float* __restrict__ gb1,
                                                   const float* __restrict__ gw2,
                                                   const float* __restrict__ gb2,
                                                   const float* __restrict__ pw,
                                                   const float* __restrict__ pb,
                                                   float* __restrict__ out) {
    extern __shared__ float tsm[];
    float* embs_s = tsm;                    // [KK][HH]
    float* red    = tsm + KK * HH;          // [KK][16]
    int b = blockIdx.x;
    int tid = threadIdx.x;
    int lane = tid & 31, warp = tid >> 5;   // 16 warps

    // 1. embs (each thread: 2 h-values per k)
    #pragma unroll
    for (int k = 0; k < KK; k++) {
        int idx = g_topidx[b * KK + k];
        int l = idx / PP, p = idx % PP;
        int e = min(l + p, LL - 1);
        float inv = 1.f / (float)(p + 1);
        #pragma unroll
        for (int i = 0; i < 2; i++) {
            int h = tid + i * 512;
            float s = 0.f;
            for (int t = l; t <= e; t++) s += hidden[((size_t)(b * LL + t)) * HH + h];
            embs_s[k * HH + h] = s * inv;
        }
    }
    __syncthreads();

    // 2. g1 + gate partials: o = tid
    {
        float tacc[KK];
        #pragma unroll
        for (int k = 0; k < KK; k++) tacc[k] = 0.f;
        for (int m = 0; m < HH; m++) {
            float g = gw1[(size_t)m * 512 + tid];
            #pragma unroll
            for (int k = 0; k < KK; k++) tacc[k] = fmaf(embs_s[k * HH + m], g, tacc[k]);
        }
        float gb = gb1[tid], gv = gw2[tid];
        float part[KK];
        #pragma unroll
        for (int k = 0; k < KK; k++) part[k] = tanhf(tacc[k] + gb) * gv;
        // warp reduce each k, then cross-warp via smem
        #pragma unroll
        for (int k = 0; k < KK; k++) {
            float v = part[k];
            for (int o = 16; o; o >>= 1) v += __shfl_down_sync(0xffffffffu, v, o);
            if (lane == 0) red[k * 16 + warp] = v;
        }
    }
    __syncthreads();
    if (tid == 0) {
        float gate[KK];
        float g2b = gb2[0];
        #pragma unroll
        for (int k = 0; k < KK; k++) {
            float v = 0.f;
            #pragma unroll
            for (int w = 0; w < 16; w++) v += red[k * 16 + w];
            gate[k] = v + g2b;
        }
        float mx = gate[0];
        #pragma unroll
        for (int k = 1; k < KK; k++) mx = fmaxf(mx, gate[k]);
        float ex[KK], ssum = 0.f;
        #pragma unroll
        for (int k = 0; k < KK; k++) { ex[k] = expf(gate[k] - mx); ssum += ex[k]; }
        float rs = 1.f / ssum;
        #pragma unroll
        for (int k = 0; k < KK; k++) {
            out[OFF_ATTN + b * KK + k] = ex[k] * rs;
            out[OFF_PMASK + b * KK + k] = 1.0f;
        }
    }

    // 4. phrase: d = tid&127, kg = tid>>7 handles k = j*4+kg
    {
        int d = tid & 127, kg = tid >> 7;
        float pacc[4] = {0.f, 0.f, 0.f, 0.f};
        for (int m = 0; m < HH; m++) {
            float pv = pw[(size_t)m * PDD + d];
            #pragma unroll
            for (int j = 0; j < 4; j++)
                pacc[j] = fmaf(embs_s[(j * 4 + kg) * HH + m], pv, pacc[j]);
        }
        float pbv = pb[d];
        #pragma unroll
        for (int j = 0; j < 4; j++)
            out[(size_t)(b * KK + j * 4 + kg) * PDD + d] = pacc[j] + pbv;
    }
}

// ===========================================================================
extern "C" void kernel_launch(void* const* d_in, const int* in_sizes, int n_in,
                              void* d_out, int out_size) {
    const float* hidden  = (const float*)d_in[0];
    const int*   lengths = (const int*)  d_in[1];
    const float* w1      = (const float*)d_in[2];
    const float* b1      = (const float*)d_in[3];
    const float* w2      = (const float*)d_in[4];
    const float* b2      = (const float*)d_in[5];
    const float* gw1     = (const float*)d_in[6];
    const float* gb1     = (const float*)d_in[7];
    const float* gw2     = (const float*)d_in[8];
    const float* gb2     = (const float*)d_in[9];
    const float* pw      = (const float*)d_in[10];
    const float* pb      = (const float*)d_in[11];
    float* out = (float*)d_out;

    cudaFuncSetAttribute(gemm_mma_kernel, cudaFuncAttributeMaxDynamicSharedMemorySize, GSMEM_SZ);
    cudaFuncSetAttribute(tail_kernel, cudaFuncAttributeMaxDynamicSharedMemorySize, TAIL_SMEM);

    prep_b_kernel<<<dim3(NN / 32, HH / 32), dim3(32, 32)>>>(w1);
    conv_a_kernel<<<(MM * HH / 4 + 255) / 256, 256>>>(hidden);
    gemm_mma_kernel<<<dim3(NN / TN, MM / TM), 256, GSMEM_SZ>>>();
    score_kernel<<<dim3(LL, BB), 256>>>(b1, w2, b2, lengths);
    topk_kernel<<<BB, 256>>>(out);
    tail_kernel<<<BB, 512, TAIL_SMEM>>>(hidden, gw1, gb1, gw2, gb2, pw, pb, out);
}

// round 15
// speedup vs baseline: 1.0464x; 1.0091x over previous
#include <cuda_runtime.h>
#include <cuda_bf16.h>
#include <math.h>
#include <stdint.h>

// Problem constants
#define BB 16      // batch
#define LL 512     // seq len
#define HH 1024    // hidden
#define PP 5       // max phrase len
#define KK 16      // top-k
#define PDD 128    // phrase dim
#define NN 3072    // combined GEMM output cols (S | E | M)
#define MM (BB*LL) // 8192 gemm rows
#define KSPLIT 3072 // logical packed split-K: [Ah | Al | Ah] x [Bh | Bh | Bl]
#define KA 2048     // stored A' cols: [Ah | Al] (3rd block == 1st)
#define KB 2048     // stored B' cols: [Bh | Bl] (2nd block == 1st)

// Output layout: phrase[16,16,128] | pmask[16,16] | attn[16,16] | top_scores[16,16]
#define OFF_PMASK   (BB*KK*PDD)          // 32768
#define OFF_ATTN    (OFF_PMASK + BB*KK)  // 33024
#define OFF_TSCORE  (OFF_ATTN + BB*KK)   // 33280

// Scratch (static device globals — no allocation allowed)
__device__ __align__(16) __nv_bfloat16 g_Abf[(size_t)MM * KA];     // 32 MB  A' split (dedup)
__device__ __align__(16) __nv_bfloat16 g_Bbf[(size_t)NN * KB];     // 12 MB  B' split (dedup)
__device__ float g_Y[(size_t)MM * NN];                             // 96 MB  S|E|M rows
__device__ float g_scores[BB * LL * PP];
__device__ int   g_topidx[BB * KK];

// ===========================================================================
// mma.sync / cp.async helpers (base ISA, works on plain sm_100 target)
// ===========================================================================
__device__ __forceinline__ uint32_t smem_u32(const void* p) {
    uint32_t a;
    asm("{ .reg .u64 t; cvta.to.shared.u64 t, %1; cvt.u32.u64 %0, t; }" : "=r"(a) : "l"(p));
    return a;
}
#define LDSM_X4(r, addr) \
    asm volatile("ldmatrix.sync.aligned.m8n8.x4.shared.b16 {%0,%1,%2,%3}, [%4];" \
        : "=r"((r)[0]), "=r"((r)[1]), "=r"((r)[2]), "=r"((r)[3]) : "r"(addr))
#define MMA16816(c, A, b0v, b1v) \
    asm volatile("mma.sync.aligned.m16n8k16.row.col.f32.bf16.bf16.f32 " \
        "{%0,%1,%2,%3}, {%4,%5,%6,%7}, {%8,%9}, {%0,%1,%2,%3};" \
        : "+f"((c)[0]), "+f"((c)[1]), "+f"((c)[2]), "+f"((c)[3]) \
        : "r"((A)[0]), "r"((A)[1]), "r"((A)[2]), "r"((A)[3]), "r"(b0v), "r"(b1v))
#define CP_ASYNC16(saddr, gptr) \
    asm volatile("cp.async.cg.shared.global [%0], [%1], 16;" :: "r"(saddr), "l"(gptr) : "memory")
#define CP_COMMIT() asm volatile("cp.async.commit_group;" ::: "memory")
#define CP_WAIT0()  asm volatile("cp.async.wait_group 0;" ::: "memory")

// ===========================================================================
// prep_b (fused prep_u + conv_b): build U = [A1-A4 | A2+A4 | A3] tile in smem
// directly from w1 [4096,1024], transpose, emit bf16 hi/lo into
// g_Bbf [3072 n, 2048 k'] = [Bh | Bl]. No g_U round-trip, no Bh duplicate.
// feat = [start; end; mean; end-start] is linear in 3 vectors:
//   W1^T feat = (A1-A4)^T start + (A2+A4)^T end + A3^T mean
// ===========================================================================
__global__ void prep_b_kernel(const float* __restrict__ w1) {
    __shared__ float t[32][33];
    int n0 = blockIdx.x * 32, k0 = blockIdx.y * 32;
    int tx = threadIdx.x, ty = threadIdx.y;
    int r = k0 + ty;            // U row = input dim k
    int n = n0 + tx;            // U col = output n
    float v;
    if (n < 1024) {
        v = w1[r * HH + n] - w1[(3072 + r) * HH + n];
    } else if (n < 2048) {
        int h = n - 1024;
        v = w1[(1024 + r) * HH + h] + w1[(3072 + r) * HH + h];
    } else {
        int h = n - 2048;
        v = w1[(2048 + r) * HH + h];
    }
    t[ty][tx] = v;
    __syncthreads();
    float u = t[tx][ty];        // = U[k0+tx][n0+ty]
    __nv_bfloat16 hi = __float2bfloat16(u);
    __nv_bfloat16 lo = __float2bfloat16(u - __bfloat162float(hi));
    size_t base = (size_t)(n0 + ty) * KB + k0 + tx;
    g_Bbf[base]        = hi;
    g_Bbf[base + 1024] = lo;
}

// ===========================================================================
// conv_a: hidden fp32 [8192,1024] -> A' bf16 [8192, 2048] = [Ah | Al]
// ===========================================================================
__global__ void conv_a_kernel(const float* __restrict__ hidden) {
    int i = blockIdx.x * blockDim.x + threadIdx.x;   // one thread per 4 elems
    if (i >= MM * HH / 4) return;
    int r = i / (HH / 4);
    int k = (i % (HH / 4)) * 4;
    float4 v = *(const float4*)&hidden[(size_t)r * HH + k];
    __nv_bfloat16 h[4], l[4];
    float f[4] = {v.x, v.y, v.z, v.w};
    #pragma unroll
    for (int j = 0; j < 4; j++) {
        h[j] = __float2bfloat16(f[j]);
        l[j] = __float2bfloat16(f[j] - __bfloat162float(h[j]));
    }
    size_t base = (size_t)r * KA + k;
    *(uint2*)&g_Abf[base]        = *(uint2*)h;   // Ah
    *(uint2*)&g_Abf[base + 1024] = *(uint2*)l;   // Al
}

// ===========================================================================
// Tensor-core GEMM over logical K' = 3072: region map
//   K' [0,1024):    Ah x Bh   -> A ko, B ko
//   K' [1024,2048): Al x Bh   -> A ko, B ko-1024
//   K' [2048,3072): Ah x Bl   -> A ko-2048, B ko-1024
// g_Y[8192,3072] = A'[.,K'] @ B'[.,K']^T. mma.sync m16n8k16 bf16, fp32 acc.
// R12-measured best config: CTA tile 128x128, BK=64, 256 threads = 8 warps
// (4 M x 2 N), warp tile 32x64. 2-stage cp.async double buffer (73.7 KB)
// -> 2 CTAs/SM = 16 warps/SM. Rows padded to 72 bf16: conflict-free ldsm.
// ===========================================================================
#define TM 128
#define TN 128
#define BKC 64
#define NKT (KSPLIT / BKC)   // 48
#define PAD 72
#define ABUF_BYTES (128 * PAD * 2)             // 18432
#define GSMEM_SZ   (4 * ABUF_BYTES)            // 73728 (A0,A1,B0,B1)

__global__ __launch_bounds__(256, 2) void gemm_mma_kernel() {
    extern __shared__ char smem[];
    const int tid = threadIdx.x;
    const int lane = tid & 31, wid = tid >> 5;
    const int wm = wid >> 1, wn = wid & 1;       // 4x2 warp grid, 32x64 tiles
    const int bm = blockIdx.y * TM, bn = blockIdx.x * TN;
    const uint32_t sb = smem_u32(smem);

    #define SA(s)   ((uint32_t)((s) * ABUF_BYTES))
    #define SBUF(s) ((uint32_t)(2 * ABUF_BYTES + (s) * ABUF_BYTES))

    float acc[2][8][4];
    #pragma unroll
    for (int i = 0; i < 2; i++)
        #pragma unroll
        for (int j = 0; j < 8; j++)
            #pragma unroll
            for (int q = 0; q < 4; q++) acc[i][j][q] = 0.f;

    // cp.async fill: 1024 16B chunks per tile, 256 threads -> 4 chunks each
    auto load_stage = [&](int kt, int buf) {
        size_t ko = (size_t)kt * BKC;
        size_t ko_a = (ko < 2048) ? ko : ko - 2048;   // dedup: 3rd A block == 1st
        size_t ko_b = (ko < 1024) ? ko : ko - 1024;   // dedup: 2nd B block == 1st
        #pragma unroll
        for (int it = 0; it < 4; it++) {
            int id = tid + it * 256;
            int r = id >> 3, kc = (id & 7) * 8;
            CP_ASYNC16(sb + SA(buf) + (uint32_t)(r * PAD + kc) * 2,
                       &g_Abf[(size_t)(bm + r) * KA + ko_a + kc]);
            CP_ASYNC16(sb + SBUF(buf) + (uint32_t)(r * PAD + kc) * 2,
                       &g_Bbf[(size_t)(bn + r) * KB + ko_b + kc]);
        }
        CP_COMMIT();
    };

    load_stage(0, 0);

    // per-thread ldmatrix pieces
    const int rowsel = lane & 15;
    const int kl = (lane >> 4) * 8;   // k half-select

    for (int kt = 0; kt < NKT; kt++) {
        CP_WAIT0();
        __syncthreads();
        if (kt + 1 < NKT) load_stage(kt + 1, (kt + 1) & 1);

        const int cur = kt & 1;
        const uint32_t abase = sb + SA(cur);
        const uint32_t bbase = sb + SBUF(cur);
        #pragma unroll
        for (int kk = 0; kk < BKC; kk += 16) {
            uint32_t af[2][4], bf[4][4];
            #pragma unroll
            for (int mi = 0; mi < 2; mi++)
                LDSM_X4(af[mi], abase + (uint32_t)((wm * 32 + mi * 16 + rowsel) * PAD + kk + kl) * 2);
            #pragma unroll
            for (int nj = 0; nj < 4; nj++)
                LDSM_X4(bf[nj], bbase + (uint32_t)((wn * 64 + nj * 16 + rowsel) * PAD + kk + kl) * 2);
            #pragma unroll
            for (int mi = 0; mi < 2; mi++) {
                #pragma unroll
                for (int nj = 0; nj < 4; nj++) {
                    MMA16816(acc[mi][2 * nj],     af[mi], bf[nj][0], bf[nj][2]);
                    MMA16816(acc[mi][2 * nj + 1], af[mi], bf[nj][1], bf[nj][3]);
                }
            }
        }
        // next iteration's CP_WAIT0 + sync guards buffer reuse
    }

    // epilogue: rows bm+wm*32+mi*16+(lane>>2)(+8), cols bn+wn*64+ni*8+2*(lane&3)
    #pragma unroll
    for (int mi = 0; mi < 2; mi++) {
        int gm = bm + wm * 32 + mi * 16 + (lane >> 2);
        #pragma unroll
        for (int ni = 0; ni < 8; ni++) {
            int gn = bn + wn * 64 + ni * 8 + 2 * (lane & 3);
            *(float2*)&g_Y[(size_t)gm * NN + gn] =
                make_float2(acc[mi][ni][0], acc[mi][ni][1]);
            *(float2*)&g_Y[(size_t)(gm + 8) * NN + gn] =
                make_float2(acc[mi][ni][2], acc[mi][ni][3]);
        }
    }
}

// ===========================================================================
// Scoring: z = S[l] + E[e] + (sum M[l..l+p])/(p+1) + b1;
// score = sum relu(z)*w2 + b2 (or -inf). One block per (b,l).
// ===========================================================================
__global__ __launch_bounds__(256) void score_kernel(const float* __restrict__ b1,
                                                    const float* __restrict__ w2,
                                                    const float* __restrict__ b2,
                                                    const int* __restrict__ lengths) {
    int l = blockIdx.x;
    int b = blockIdx.y;
    int tid = threadIdx.x;
    size_t rowbase = (size_t)(b * LL + l) * NN;

    int h0 = tid, h1 = tid + 256, h2 = tid + 512, h3 = tid + 768;
    float s0 = g_Y[rowbase + h0], s1 = g_Y[rowbase + h1];
    float s2 = g_Y[rowbase + h2], s3 = g_Y[rowbase + h3];
    float w0 = w2[h0], w1v = w2[h1], w2v = w2[h2], w3v = w2[h3];
    float c0 = b1[h0], c1 = b1[h1], c2 = b1[h2], c3 = b1[h3];
    float m0 = 0.f, m1 = 0.f, m2 = 0.f, m3 = 0.f;

    float acc[PP];
    #pragma unroll
    for (int p = 0; p < PP; p++) {
        int t = l + p;
        if (t <= LL - 1) {
            size_t mb = (size_t)(b * LL + t) * NN + 2048;
            m0 += g_Y[mb + h0]; m1 += g_Y[mb + h1];
            m2 += g_Y[mb + h2]; m3 += g_Y[mb + h3];
        }
        int e = min(t, LL - 1);
        size_t eb = (size_t)(b * LL + e) * NN + 1024;
        float inv = 1.f / (float)(p + 1);
        float z0 = s0 + g_Y[eb + h0] + m0 * inv + c0;
        float z1 = s1 + g_Y[eb + h1] + m1 * inv + c1;
        float z2 = s2 + g_Y[eb + h2] + m2 * inv + c2;
        float z3 = s3 + g_Y[eb + h3] + m3 * inv + c3;
        acc[p] = fmaxf(z0, 0.f) * w0 + fmaxf(z1, 0.f) * w1v
               + fmaxf(z2, 0.f) * w2v + fmaxf(z3, 0.f) * w3v;
    }

    __shared__ float red[8][PP];
    int lane = tid & 31, warp = tid >> 5;
    #pragma unroll
    for (int p = 0; p < PP; p++) {
        float v = acc[p];
        for (int o = 16; o; o >>= 1) v += __shfl_down_sync(0xffffffffu, v, o);
        if (lane == 0) red[warp][p] = v;
    }
    __syncthreads();
    if (tid < PP) {
        float v = 0.f;
        #pragma unroll
        for (int w = 0; w < 8; w++) v += red[w][tid];
        int len = lengths[b];
        float bias2 = b2[0];
        g_scores[b * (LL * PP) + l * PP + tid] =
            (l + tid < len) ? (v + bias2) : -INFINITY;
    }
}

// ===========================================================================
// Top-K per batch (iterative argmax, ties -> lower index).
// Warp-shfl reduction: 2 barriers per k instead of 8.
// ===========================================================================
__global__ void topk_kernel(float* __restrict__ out) {
    int b = blockIdx.x;
    int tid = threadIdx.x;  // 256
    int lane = tid & 31, warp = tid >> 5;
    __shared__ float sv[LL * PP];
    __shared__ float wv[8];
    __shared__ int   wi[8];
    for (int i = tid; i < LL * PP; i += 256) sv[i] = g_scores[b * (LL * PP) + i];
    __syncthreads();
    for (int k = 0; k < KK; k++) {
        float best = -INFINITY; int besti = 0x7fffffff;
        for (int i = tid; i < LL * PP; i += 256) {
            float v = sv[i];
            if (v > best || (v == best && i < besti)) { best = v; besti = i; }
        }
        // warp reduce via shfl (tie -> lower index)
        #pragma unroll
        for (int o = 16; o; o >>= 1) {
            float ov = __shfl_down_sync(0xffffffffu, best, o);
            int   oi = __shfl_down_sync(0xffffffffu, besti, o);
            if (ov > best || (ov == best && oi < besti)) { best = ov; besti = oi; }
        }
        if (lane == 0) { wv[warp] = best; wi[warp] = besti; }
        __syncthreads();
        if (tid == 0) {
            float fb = wv[0]; int fi = wi[0];
            #pragma unroll
            for (int w = 1; w < 8; w++) {
                if (wv[w] > fb || (wv[w] == fb && wi[w] < fi)) { fb = wv[w]; fi = wi[w]; }
            }
            g_topidx[b * KK + k] = fi;
            out[OFF_TSCORE + b * KK + k] = fb;
            sv[fi] = -INFINITY;
        }
        __syncthreads();
    }
}

// ===========================================================================
// Fused tail: one block per batch b (512 threads).
//  1. embs[k,:] = mean of hidden rows (into 64KB smem; no global round-trip)
//  2. G1 = tanh(embs @ gw1 + gb1), gate = G1 @ gw2 + gb2 (block reduction)
//  3. attn = softmax(gate), pmask = 1
//  4. phrase = embs @ pw + pb
// ===========================================================================
#define TAIL_SMEM (KK * HH * 4 + KK * 16 * 4)   // 65536 + 1024

__global__ __launch_bounds__(512) void tail_kernel(const float* __restrict__ hidden,
                                                   const float* __restrict__ gw1,
                                                   const float* __restrict__ gb1,
                                                   const float* __restrict__ gw2,
                                                   const float* __restrict__ gb2,
                                                   const float* __restrict__ pw,
                                                   const float* __restrict__ pb,
                                                   float* __restrict__ out) {
    extern __shared__ float tsm[];
    float* embs_s = tsm;                    // [KK][HH]
    float* red    = tsm + KK * HH;          // [KK][16]
    int b = blockIdx.x;
    int tid = threadIdx.x;
    int lane = tid & 31, warp = tid >> 5;   // 16 warps

    // 1. embs (each thread: 2 h-values per k)
    #pragma unroll
    for (int k = 0; k < KK; k++) {
        int idx = g_topidx[b * KK + k];
        int l = idx / PP, p = idx % PP;
        int e = min(l + p, LL - 1);
        float inv = 1.f / (float)(p + 1);
        #pragma unroll
        for (int i = 0; i < 2; i++) {
            int h = tid + i * 512;
            float s = 0.f;
            for (int t = l; t <= e; t++) s += hidden[((size_t)(b * LL + t)) * HH + h];
            embs_s[k * HH + h] = s * inv;
        }
    }
    __syncthreads();

    // 2. g1 + gate partials: o = tid
    {
        float tacc[KK];
        #pragma unroll
        for (int k = 0; k < KK; k++) tacc[k] = 0.f;
        for (int m = 0; m < HH; m++) {
            float g = gw1[(size_t)m * 512 + tid];
            #pragma unroll
            for (int k = 0; k < KK; k++) tacc[k] = fmaf(embs_s[k * HH + m], g, tacc[k]);
        }
        float gb = gb1[tid], gv = gw2[tid];
        float part[KK];
        #pragma unroll
        for (int k = 0; k < KK; k++) part[k] = tanhf(tacc[k] + gb) * gv;
        // warp reduce each k, then cross-warp via smem
        #pragma unroll
        for (int k = 0; k < KK; k++) {
            float v = part[k];
            for (int o = 16; o; o >>= 1) v += __shfl_down_sync(0xffffffffu, v, o);
            if (lane == 0) red[k * 16 + warp] = v;
        }
    }
    __syncthreads();
    if (tid == 0) {
        float gate[KK];
        float g2b = gb2[0];
        #pragma unroll
        for (int k = 0; k < KK; k++) {
            float v = 0.f;
            #pragma unroll
            for (int w = 0; w < 16; w++) v += red[k * 16 + w];
            gate[k] = v + g2b;
        }
        float mx = gate[0];
        #pragma unroll
        for (int k = 1; k < KK; k++) mx = fmaxf(mx, gate[k]);
        float ex[KK], ssum = 0.f;
        #pragma unroll
        for (int k = 0; k < KK; k++) { ex[k] = expf(gate[k] - mx); ssum += ex[k]; }
        float rs = 1.f / ssum;
        #pragma unroll
        for (int k = 0; k < KK; k++) {
            out[OFF_ATTN + b * KK + k] = ex[k] * rs;
            out[OFF_PMASK + b * KK + k] = 1.0f;
        }
    }

    // 4. phrase: d = tid&127, kg = tid>>7 handles k = j*4+kg
    {
        int d = tid & 127, kg = tid >> 7;
        float pacc[4] = {0.f, 0.f, 0.f, 0.f};
        for (int m = 0; m < HH; m++) {
            float pv = pw[(size_t)m * PDD + d];
            #pragma unroll
            for (int j = 0; j < 4; j++)
                pacc[j] = fmaf(embs_s[(j * 4 + kg) * HH + m], pv, pacc[j]);
        }
        float pbv = pb[d];
        #pragma unroll
        for (int j = 0; j < 4; j++)
            out[(size_t)(b * KK + j * 4 + kg) * PDD + d] = pacc[j] + pbv;
    }
}

// ===========================================================================
extern "C" void kernel_launch(void* const* d_in, const int* in_sizes, int n_in,
                              void* d_out, int out_size) {
    const float* hidden  = (const float*)d_in[0];
    const int*   lengths = (const int*)  d_in[1];
    const float* w1      = (const float*)d_in[2];
    const float* b1      = (const float*)d_in[3];
    const float* w2      = (const float*)d_in[4];
    const float* b2      = (const float*)d_in[5];
    const float* gw1     = (const float*)d_in[6];
    const float* gb1     = (const float*)d_in[7];
    const float* gw2     = (const float*)d_in[8];
    const float* gb2     = (const float*)d_in[9];
    const float* pw      = (const float*)d_in[10];
    const float* pb      = (const float*)d_in[11];
    float* out = (float*)d_out;

    cudaFuncSetAttribute(gemm_mma_kernel, cudaFuncAttributeMaxDynamicSharedMemorySize, GSMEM_SZ);
    cudaFuncSetAttribute(tail_kernel, cudaFuncAttributeMaxDynamicSharedMemorySize, TAIL_SMEM);

    prep_b_kernel<<<dim3(NN / 32, HH / 32), dim3(32, 32)>>>(w1);
    conv_a_kernel<<<(MM * HH / 4 + 255) / 256, 256>>>(hidden);
    gemm_mma_kernel<<<dim3(NN / TN, MM / TM), 256, GSMEM_SZ>>>();
    score_kernel<<<dim3(LL, BB), 256>>>(b1, w2, b2, lengths);
    topk_kernel<<<BB, 256>>>(out);
    tail_kernel<<<BB, 512, TAIL_SMEM>>>(hidden, gw1, gb1, gw2, gb2, pw, pb, out);
}